// round 15
// baseline (speedup 1.0000x reference)
#include <cuda_runtime.h>
#include <cstdint>
#include <cstddef>

#define T_STEPS 512
#define BATCH   64
#define INDIM   512
#define HID     512
#define G4      2048   // 4*HID

// scratch: precomputed x@W+b, transposed tf32 W, ping-pong tf32 hidden state
__device__ float g_xw[(size_t)T_STEPS * BATCH * G4];
__device__ float g_Wt[(size_t)G4 * INDIM];
__device__ float g_atf[2][BATCH * HID];
#define NGROUPS 4
#define GCTAS   32
// per-CTA barrier flags, each on its own 128B line: g_flags[group][cta*32]
__device__ unsigned g_flags[NGROUPS][GCTAS * 32];

__device__ __forceinline__ uint32_t f2tf32(float f) {
  uint32_t r;
  asm("cvt.rna.tf32.f32 %0, %1;" : "=r"(r) : "f"(f));
  return r;
}
__device__ __forceinline__ float f2tf32f(float f) {
  return __uint_as_float(f2tf32(f));
}
__device__ __forceinline__ uint32_t smem_u32(const void* p) {
  uint32_t a;
  asm("{ .reg .u64 t; cvta.to.shared.u64 t, %1; cvt.u32.u64 %0, t; }"
      : "=r"(a) : "l"(p));
  return a;
}
__device__ __forceinline__ void ldsm_x4(uint32_t* d, uint32_t addr) {
  asm volatile("ldmatrix.sync.aligned.m8n8.x4.shared.b16 {%0,%1,%2,%3}, [%4];"
               : "=r"(d[0]), "=r"(d[1]), "=r"(d[2]), "=r"(d[3]) : "r"(addr));
}

__device__ __forceinline__ void mma_tf32(float* d, const uint32_t* a,
                                         const uint32_t* b) {
  asm volatile(
      "mma.sync.aligned.m16n8k8.row.col.f32.tf32.tf32.f32 "
      "{%0,%1,%2,%3}, {%4,%5,%6,%7}, {%8,%9}, {%0,%1,%2,%3};"
      : "+f"(d[0]), "+f"(d[1]), "+f"(d[2]), "+f"(d[3])
      : "r"(a[0]), "r"(a[1]), "r"(a[2]), "r"(a[3]), "r"(b[0]), "r"(b[1]));
}

// ---------------------------------------------------------------------------
// W transpose + tf32 rounding; rounds a0 into g_atf[0]; zeroes barrier flags.
// ---------------------------------------------------------------------------
__global__ __launch_bounds__(256) void transpose_kernel(const float* __restrict__ W,
                                                        const float* __restrict__ a0) {
  __shared__ float tile[32][33];
  const int n0 = blockIdx.x * 32, k0 = blockIdx.y * 32;
  const int tx = threadIdx.x, ty = threadIdx.y;  // 32 x 8
#pragma unroll
  for (int i = 0; i < 32; i += 8)
    tile[ty + i][tx] = W[(size_t)(k0 + ty + i) * G4 + n0 + tx];
  __syncthreads();
#pragma unroll
  for (int i = 0; i < 32; i += 8)
    g_Wt[(size_t)(n0 + ty + i) * INDIM + k0 + tx] = f2tf32f(tile[tx][ty + i]);
  if (blockIdx.y == 0) {  // 64 blocks x 256 thr: round a0 (32768 elems)
    const int fl = blockIdx.x * 256 + ty * 32 + tx;
    g_atf[0][fl] = f2tf32f(a0[fl]);
    g_atf[0][fl + 16384] = f2tf32f(a0[fl + 16384]);
  }
  if (blockIdx.x == 0 && blockIdx.y == 0) {  // zero all flags (4096 u32)
    const int lt = ty * 32 + tx;
#pragma unroll
    for (int j = 0; j < NGROUPS * GCTAS * 32 / 256; ++j)
      ((unsigned*)g_flags)[lt + j * 256] = 0u;
  }
}

// ---------------------------------------------------------------------------
// TF32 tensor-core GEMM (unchanged, known-good): g_xw = x@W + bias
// ---------------------------------------------------------------------------
#define BM 128
#define BN 128
#define BK 32
#define SSTR 36

__global__ __launch_bounds__(256) void xw_tc_kernel(const float* __restrict__ A,
                                                    const float* __restrict__ bias) {
  extern __shared__ float smem[];
  float* As[2] = {smem, smem + BM * SSTR};
  float* Bs[2] = {smem + 2 * BM * SSTR, smem + 3 * BM * SSTR};

  const int tid = threadIdx.x;
  const int lane = tid & 31, wid = tid >> 5;
  const int wm = (wid >> 2) * 64;
  const int wn = (wid & 3) * 32;
  const int g = lane >> 2, tg = lane & 3;
  const int n0 = blockIdx.x * BN;
  const int m0 = blockIdx.y * BM;

  const int lr = tid >> 3;
  const int lc = (tid & 7) * 4;

  float acc[4][4][4];
#pragma unroll
  for (int i = 0; i < 4; ++i)
#pragma unroll
    for (int j = 0; j < 4; ++j)
#pragma unroll
      for (int q = 0; q < 4; ++q) acc[i][j][q] = 0.0f;

  float4 pa[4], pb[4];
#pragma unroll
  for (int j = 0; j < 4; ++j) {
    const int r = lr + j * 32;
    pa[j] = *(const float4*)(A + (size_t)(m0 + r) * INDIM + lc);
    pb[j] = *(const float4*)(g_Wt + (size_t)(n0 + r) * INDIM + lc);
  }

  const int NKT = INDIM / BK;  // 16
  for (int kt = 0; kt < NKT; ++kt) {
    const int s = kt & 1;
#pragma unroll
    for (int j = 0; j < 4; ++j) {
      const int r = lr + j * 32;
      float* ap = As[s] + r * SSTR + lc;
      ap[0] = f2tf32f(pa[j].x);
      ap[1] = f2tf32f(pa[j].y);
      ap[2] = f2tf32f(pa[j].z);
      ap[3] = f2tf32f(pa[j].w);
      *(float4*)(Bs[s] + r * SSTR + lc) = pb[j];
    }
    __syncthreads();

    if (kt + 1 < NKT) {
      const int ko = (kt + 1) * BK;
#pragma unroll
      for (int j = 0; j < 4; ++j) {
        const int r = lr + j * 32;
        pa[j] = *(const float4*)(A + (size_t)(m0 + r) * INDIM + ko + lc);
        pb[j] = *(const float4*)(g_Wt + (size_t)(n0 + r) * INDIM + ko + lc);
      }
    }

#pragma unroll
    for (int k8 = 0; k8 < 4; ++k8) {
      const int kb = k8 * 8;
      uint32_t afr[4][4], bfr[4][2];
#pragma unroll
      for (int mf = 0; mf < 4; ++mf) {
        const float* ap = As[s] + (wm + mf * 16) * SSTR + kb;
        afr[mf][0] = __float_as_uint(ap[g * SSTR + tg]);
        afr[mf][1] = __float_as_uint(ap[(g + 8) * SSTR + tg]);
        afr[mf][2] = __float_as_uint(ap[g * SSTR + tg + 4]);
        afr[mf][3] = __float_as_uint(ap[(g + 8) * SSTR + tg + 4]);
      }
#pragma unroll
      for (int nf = 0; nf < 4; ++nf) {
        const float* bp = Bs[s] + (wn + nf * 8) * SSTR + kb;
        bfr[nf][0] = __float_as_uint(bp[g * SSTR + tg]);
        bfr[nf][1] = __float_as_uint(bp[g * SSTR + tg + 4]);
      }
#pragma unroll
      for (int mf = 0; mf < 4; ++mf)
#pragma unroll
        for (int nf = 0; nf < 4; ++nf)
          mma_tf32(acc[mf][nf], afr[mf], bfr[nf]);
    }
    __syncthreads();
  }

  float2 bv[4];
#pragma unroll
  for (int nf = 0; nf < 4; ++nf)
    bv[nf] = *(const float2*)(bias + n0 + wn + nf * 8 + tg * 2);
#pragma unroll
  for (int mf = 0; mf < 4; ++mf) {
    const int row0 = m0 + wm + mf * 16 + g;
#pragma unroll
    for (int nf = 0; nf < 4; ++nf) {
      const int col = n0 + wn + nf * 8 + tg * 2;
      float2 v0 = make_float2(acc[mf][nf][0] + bv[nf].x, acc[mf][nf][1] + bv[nf].y);
      float2 v1 = make_float2(acc[mf][nf][2] + bv[nf].x, acc[mf][nf][3] + bv[nf].y);
      *(float2*)(g_xw + (size_t)row0 * G4 + col) = v0;
      *(float2*)(g_xw + (size_t)(row0 + 8) * G4 + col) = v1;
    }
  }
}

// ---------------------------------------------------------------------------
// Persistent TC recurrence, batch-split into 4 groups of 16 rows x 32 CTAs.
// This round: FINE-GRAINED staging — each warp polls its 4 producer CTAs'
// flags and loads their 16x16 slices as they arrive; the two K-halves sync
// independently (bar.sync 1 / 2) so staging overlaps the arrival spread.
// ---------------------------------------------------------------------------
#define GBATCH   16
#define RTHREADS 256
#define ASTR 516   // smem row stride (floats)
#define GSTR 68    // gate tile row stride (64 + 4 pad)

__device__ __forceinline__ float sigmoidf_(float x) {
  return __fdividef(1.0f, 1.0f + __expf(-x));
}
__device__ __forceinline__ float ftanh_(float x) {
  const float e = __expf(-2.0f * fabsf(x));
  const float r = __fdividef(1.0f - e, 1.0f + e);
  return copysignf(r, x);
}

__global__ __launch_bounds__(RTHREADS) void recur_tc_kernel(
    const float* __restrict__ U, float* __restrict__ out) {
  extern __shared__ float sm[];
  float* As = sm;                              // 16 x ASTR
  float* Us = sm + GBATCH * ASTR;              // 64 x ASTR
  float* Gs = sm + GBATCH * ASTR + 64 * ASTR;  // 2 x 16 x GSTR

  const int tid = threadIdx.x;
  const int lane = tid & 31, wid = tid >> 5;
  const int g = lane >> 2, tg = lane & 3;
  const int kw = wid >> 2;                 // K-half (0,1)
  const int nq = wid & 3;                  // n-quarter (0..3)
  const int kb0 = kw * 256;
  const int group = blockIdx.x >> 5;       // 0..3 (batch group)
  const int cg = blockIdx.x & 31;          // CTA in group
  const int hb = cg * 16;                  // h-col base (16 h per CTA)
  const int b0 = group * GBATCH;           // global batch base
  unsigned* myflag = &g_flags[group][cg * 32];

  // --- preload U slice (tf32): Us[i*4+gate][k] = U[k][gate*512+hb+i], i<16
  for (int idx = tid; idx < 512 * 4 * 4; idx += RTHREADS) {
    const int k = idx >> 4, gate = (idx >> 2) & 3, iq = idx & 3;
    float4 v = *(const float4*)(U + (size_t)k * G4 + gate * HID + hb + iq * 4);
    Us[((iq * 4 + 0) * 4 + gate) * ASTR + k] = f2tf32f(v.x);
    Us[((iq * 4 + 1) * 4 + gate) * ASTR + k] = f2tf32f(v.y);
    Us[((iq * 4 + 2) * 4 + gate) * ASTR + k] = f2tf32f(v.z);
    Us[((iq * 4 + 3) * 4 + gate) * ASTR + k] = f2tf32f(v.w);
  }

  // ldmatrix per-lane base offsets (bytes)
  const int quad = lane >> 3, r8 = lane & 7;
  const uint32_t As_u = smem_u32(As);
  const uint32_t Us_u = smem_u32(Us);
  const uint32_t a_base =
      As_u + ((((quad & 1) * 8 + r8) * ASTR + (quad >> 1) * 4 + kb0) * 4);
  const uint32_t b_base =
      Us_u + (((nq * 16 + (quad >> 1) * 8 + r8) * ASTR + (quad & 1) * 4 + kb0) * 4);

  // acc columns in xw space: n_local = nq*16 + nf*8 + 2tg (+1)
  int colA[2], colB[2];
#pragma unroll
  for (int nf = 0; nf < 2; ++nf) {
    const int nlA = nq * 16 + nf * 8 + 2 * tg, nlB = nlA + 1;
    colA[nf] = (nlA & 3) * HID + hb + (nlA >> 2);
    colB[nf] = (nlB & 3) * HID + hb + (nlB >> 2);
  }
  const int bl = tid >> 4;                 // gate-phase local batch (0..15)
  const int hi = tid & 15;                 // gate-phase h index (0..15)

  // fine-grained staging constants: this warp loads slices of producers
  // p0..p0+3 (its own K-half); per slice, lane covers (row, 8 cols).
  const int p0 = kw * 16 + nq * 4;
  const int srow = lane >> 1;              // 0..15
  const int sc0 = (lane & 1) * 8;          // col offset 0 or 8

  // --- prefetch xw for t=0 (K-half-0 warps hold the init)
  float pxw[8];
  if (kw == 0) {
    const float* xwp = g_xw + (size_t)(b0 + g) * G4;
#pragma unroll
    for (int nf = 0; nf < 2; ++nf) {
      pxw[nf * 4 + 0] = __ldg(xwp + colA[nf]);
      pxw[nf * 4 + 1] = __ldg(xwp + colB[nf]);
      pxw[nf * 4 + 2] = __ldg(xwp + 8 * G4 + colA[nf]);
      pxw[nf * 4 + 3] = __ldg(xwp + 8 * G4 + colB[nf]);
    }
  }

  for (int t = 0; t < T_STEPS; ++t) {
    // --- acc init
    float acc[2][4];
#pragma unroll
    for (int nf = 0; nf < 2; ++nf)
#pragma unroll
      for (int q = 0; q < 4; ++q)
        acc[nf][q] = (kw == 0) ? pxw[nf * 4 + q] : 0.0f;

    // --- fine-grained staging: poll each producer, load its slice on arrival
    {
      const float* srcbase = g_atf[t & 1] + (size_t)b0 * HID;
      const unsigned tgt = (unsigned)t;
#pragma unroll
      for (int j = 0; j < 4; ++j) {
        const int p = p0 + j;
        unsigned* fp = &g_flags[group][p * 32];
        unsigned v;
        do {
          asm volatile("ld.acquire.gpu.global.u32 %0, [%1];"
                       : "=r"(v) : "l"(fp) : "memory");
        } while (v < tgt);
        const float* sp = srcbase + srow * HID + p * 16 + sc0;
        float4 v0 = __ldcg((const float4*)sp);
        float4 v1 = __ldcg((const float4*)(sp + 4));
        float* dp = As + srow * ASTR + p * 16 + sc0;
        *(float4*)dp = v0;
        *(float4*)(dp + 4) = v1;
      }
    }
    // half-CTA convergence: warps of this K-half staged all 16 slices
    asm volatile("bar.sync %0, %1;" :: "r"(1 + kw), "r"(128) : "memory");

    // --- prefetch next step's xw while mma runs
    if (kw == 0 && t + 1 < T_STEPS) {
      const float* xwp = g_xw + (size_t)(t + 1) * BATCH * G4 + (size_t)(b0 + g) * G4;
#pragma unroll
      for (int nf = 0; nf < 2; ++nf) {
        pxw[nf * 4 + 0] = __ldg(xwp + colA[nf]);
        pxw[nf * 4 + 1] = __ldg(xwp + colB[nf]);
        pxw[nf * 4 + 2] = __ldg(xwp + 8 * G4 + colA[nf]);
        pxw[nf * 4 + 3] = __ldg(xwp + 8 * G4 + colB[nf]);
      }
    }

    // --- mma: m16 x n16 over this warp's K-half, ldmatrix fragment loads
#pragma unroll 8
    for (int k8 = 0; k8 < 32; ++k8) {
      uint32_t afr[4], bb[4];
      ldsm_x4(afr, a_base + k8 * 32);
      ldsm_x4(bb, b_base + k8 * 32);
      mma_tf32(acc[0], afr, bb);
      mma_tf32(acc[1], afr, bb + 2);
    }

    // --- scatter partial preactivations (per K-half region)
    float* Gsw = Gs + kw * GBATCH * GSTR;
#pragma unroll
    for (int nf = 0; nf < 2; ++nf) {
      const int nb = nq * 16 + nf * 8 + 2 * tg;
      *(float2*)(Gsw + g * GSTR + nb) = make_float2(acc[nf][0], acc[nf][1]);
      *(float2*)(Gsw + (g + 8) * GSTR + nb) = make_float2(acc[nf][2], acc[nf][3]);
    }
    __syncthreads();

    // --- gate math: 1 output/thread (b=bl, h=hb+hi); sum the two K-halves
    {
      float4 gA = *(const float4*)(Gs + bl * GSTR + hi * 4);
      float4 gB = *(const float4*)(Gs + GBATCH * GSTR + bl * GSTR + hi * 4);
      const float gu = sigmoidf_(gA.x + gB.x);
      const float gf = sigmoidf_(gA.y + gB.y);
      const float go = sigmoidf_(gA.z + gB.z);
      const float cd = ftanh_(gA.w + gB.w);
      const float ap = As[bl * ASTR + hb + hi];  // tf32-rounded a_{t-1}
      const float ct = gu * cd + gf * ap;
      const float at = go * ftanh_(ct);
      g_atf[(t + 1) & 1][(b0 + bl) * HID + hb + hi] = f2tf32f(at);
      out[(size_t)t * BATCH * HID + (size_t)(b0 + bl) * HID + hb + hi] = at;
    }

    // --- release: all writes (and this CTA's staging reads) are done
    if (t + 1 < T_STEPS) {
      __syncthreads();  // orders all threads' writes before tid0's release
      if (tid == 0) {
        unsigned v = (unsigned)(t + 1);
        asm volatile("st.release.gpu.global.u32 [%0], %1;"
                     :: "l"(myflag), "r"(v) : "memory");
      }
    }
  }
}

// ---------------------------------------------------------------------------
extern "C" void kernel_launch(void* const* d_in, const int* in_sizes, int n_in,
                              void* d_out, int out_size) {
  (void)in_sizes; (void)n_in; (void)out_size;
  const float* x    = (const float*)d_in[0];  // [T, B, I]
  const float* a0   = (const float*)d_in[1];  // [B, H]
  const float* W    = (const float*)d_in[2];  // [I, 4H]
  const float* U    = (const float*)d_in[3];  // [H, 4H]
  const float* bias = (const float*)d_in[4];  // [4H]
  float* out = (float*)d_out;                 // [T, B, H]

  const int smemG = 4 * BM * SSTR * sizeof(float);  // 73728 B
  cudaFuncSetAttribute(xw_tc_kernel, cudaFuncAttributeMaxDynamicSharedMemorySize,
                       smemG);
  const int smemR =
      (GBATCH * ASTR + 64 * ASTR + 2 * GBATCH * GSTR) * sizeof(float);  // 173824
  cudaFuncSetAttribute(recur_tc_kernel, cudaFuncAttributeMaxDynamicSharedMemorySize,
                       smemR);

  transpose_kernel<<<dim3(G4 / 32, INDIM / 32), dim3(32, 8)>>>(W, a0);
  xw_tc_kernel<<<dim3(G4 / BN, (T_STEPS * BATCH) / BM), 256, smemG>>>(x, bias);
  recur_tc_kernel<<<NGROUPS * GCTAS, RTHREADS, smemR>>>(U, out);
}

// round 16
// speedup vs baseline: 1.6841x; 1.6841x over previous
#include <cuda_runtime.h>
#include <cstdint>
#include <cstddef>

#define T_STEPS 512
#define BATCH   64
#define INDIM   512
#define HID     512
#define G4      2048   // 4*HID

// scratch: precomputed x@W+b, transposed tf32 W, ping-pong tf32 hidden state
__device__ float g_xw[(size_t)T_STEPS * BATCH * G4];
__device__ float g_Wt[(size_t)G4 * INDIM];
__device__ float g_atf[2][BATCH * HID];
#define NGROUPS 4
#define GCTAS   32
// per-CTA barrier flags, each on its own 128B line: g_flags[group][cta*32]
__device__ unsigned g_flags[NGROUPS][GCTAS * 32];

__device__ __forceinline__ uint32_t f2tf32(float f) {
  uint32_t r;
  asm("cvt.rna.tf32.f32 %0, %1;" : "=r"(r) : "f"(f));
  return r;
}
__device__ __forceinline__ float f2tf32f(float f) {
  return __uint_as_float(f2tf32(f));
}
__device__ __forceinline__ uint32_t smem_u32(const void* p) {
  uint32_t a;
  asm("{ .reg .u64 t; cvta.to.shared.u64 t, %1; cvt.u32.u64 %0, t; }"
      : "=r"(a) : "l"(p));
  return a;
}
__device__ __forceinline__ void ldsm_x4(uint32_t* d, uint32_t addr) {
  asm volatile("ldmatrix.sync.aligned.m8n8.x4.shared.b16 {%0,%1,%2,%3}, [%4];"
               : "=r"(d[0]), "=r"(d[1]), "=r"(d[2]), "=r"(d[3]) : "r"(addr));
}

__device__ __forceinline__ void mma_tf32(float* d, const uint32_t* a,
                                         const uint32_t* b) {
  asm volatile(
      "mma.sync.aligned.m16n8k8.row.col.f32.tf32.tf32.f32 "
      "{%0,%1,%2,%3}, {%4,%5,%6,%7}, {%8,%9}, {%0,%1,%2,%3};"
      : "+f"(d[0]), "+f"(d[1]), "+f"(d[2]), "+f"(d[3])
      : "r"(a[0]), "r"(a[1]), "r"(a[2]), "r"(a[3]), "r"(b[0]), "r"(b[1]));
}

// ---------------------------------------------------------------------------
// W transpose + tf32 rounding; rounds a0 into g_atf[0]; zeroes barrier flags.
// ---------------------------------------------------------------------------
__global__ __launch_bounds__(256) void transpose_kernel(const float* __restrict__ W,
                                                        const float* __restrict__ a0) {
  __shared__ float tile[32][33];
  const int n0 = blockIdx.x * 32, k0 = blockIdx.y * 32;
  const int tx = threadIdx.x, ty = threadIdx.y;  // 32 x 8
#pragma unroll
  for (int i = 0; i < 32; i += 8)
    tile[ty + i][tx] = W[(size_t)(k0 + ty + i) * G4 + n0 + tx];
  __syncthreads();
#pragma unroll
  for (int i = 0; i < 32; i += 8)
    g_Wt[(size_t)(n0 + ty + i) * INDIM + k0 + tx] = f2tf32f(tile[tx][ty + i]);
  if (blockIdx.y == 0) {  // 64 blocks x 256 thr: round a0 (32768 elems)
    const int fl = blockIdx.x * 256 + ty * 32 + tx;
    g_atf[0][fl] = f2tf32f(a0[fl]);
    g_atf[0][fl + 16384] = f2tf32f(a0[fl + 16384]);
  }
  if (blockIdx.x == 0 && blockIdx.y == 0) {  // zero all flags (4096 u32)
    const int lt = ty * 32 + tx;
#pragma unroll
    for (int j = 0; j < NGROUPS * GCTAS * 32 / 256; ++j)
      ((unsigned*)g_flags)[lt + j * 256] = 0u;
  }
}

// ---------------------------------------------------------------------------
// TF32 tensor-core GEMM (unchanged, known-good): g_xw = x@W + bias
// ---------------------------------------------------------------------------
#define BM 128
#define BN 128
#define BK 32
#define SSTR 36

__global__ __launch_bounds__(256) void xw_tc_kernel(const float* __restrict__ A,
                                                    const float* __restrict__ bias) {
  extern __shared__ float smem[];
  float* As[2] = {smem, smem + BM * SSTR};
  float* Bs[2] = {smem + 2 * BM * SSTR, smem + 3 * BM * SSTR};

  const int tid = threadIdx.x;
  const int lane = tid & 31, wid = tid >> 5;
  const int wm = (wid >> 2) * 64;
  const int wn = (wid & 3) * 32;
  const int g = lane >> 2, tg = lane & 3;
  const int n0 = blockIdx.x * BN;
  const int m0 = blockIdx.y * BM;

  const int lr = tid >> 3;
  const int lc = (tid & 7) * 4;

  float acc[4][4][4];
#pragma unroll
  for (int i = 0; i < 4; ++i)
#pragma unroll
    for (int j = 0; j < 4; ++j)
#pragma unroll
      for (int q = 0; q < 4; ++q) acc[i][j][q] = 0.0f;

  float4 pa[4], pb[4];
#pragma unroll
  for (int j = 0; j < 4; ++j) {
    const int r = lr + j * 32;
    pa[j] = *(const float4*)(A + (size_t)(m0 + r) * INDIM + lc);
    pb[j] = *(const float4*)(g_Wt + (size_t)(n0 + r) * INDIM + lc);
  }

  const int NKT = INDIM / BK;  // 16
  for (int kt = 0; kt < NKT; ++kt) {
    const int s = kt & 1;
#pragma unroll
    for (int j = 0; j < 4; ++j) {
      const int r = lr + j * 32;
      float* ap = As[s] + r * SSTR + lc;
      ap[0] = f2tf32f(pa[j].x);
      ap[1] = f2tf32f(pa[j].y);
      ap[2] = f2tf32f(pa[j].z);
      ap[3] = f2tf32f(pa[j].w);
      *(float4*)(Bs[s] + r * SSTR + lc) = pb[j];
    }
    __syncthreads();

    if (kt + 1 < NKT) {
      const int ko = (kt + 1) * BK;
#pragma unroll
      for (int j = 0; j < 4; ++j) {
        const int r = lr + j * 32;
        pa[j] = *(const float4*)(A + (size_t)(m0 + r) * INDIM + ko + lc);
        pb[j] = *(const float4*)(g_Wt + (size_t)(n0 + r) * INDIM + ko + lc);
      }
    }

#pragma unroll
    for (int k8 = 0; k8 < 4; ++k8) {
      const int kb = k8 * 8;
      uint32_t afr[4][4], bfr[4][2];
#pragma unroll
      for (int mf = 0; mf < 4; ++mf) {
        const float* ap = As[s] + (wm + mf * 16) * SSTR + kb;
        afr[mf][0] = __float_as_uint(ap[g * SSTR + tg]);
        afr[mf][1] = __float_as_uint(ap[(g + 8) * SSTR + tg]);
        afr[mf][2] = __float_as_uint(ap[g * SSTR + tg + 4]);
        afr[mf][3] = __float_as_uint(ap[(g + 8) * SSTR + tg + 4]);
      }
#pragma unroll
      for (int nf = 0; nf < 4; ++nf) {
        const float* bp = Bs[s] + (wn + nf * 8) * SSTR + kb;
        bfr[nf][0] = __float_as_uint(bp[g * SSTR + tg]);
        bfr[nf][1] = __float_as_uint(bp[g * SSTR + tg + 4]);
      }
#pragma unroll
      for (int mf = 0; mf < 4; ++mf)
#pragma unroll
        for (int nf = 0; nf < 4; ++nf)
          mma_tf32(acc[mf][nf], afr[mf], bfr[nf]);
    }
    __syncthreads();
  }

  float2 bv[4];
#pragma unroll
  for (int nf = 0; nf < 4; ++nf)
    bv[nf] = *(const float2*)(bias + n0 + wn + nf * 8 + tg * 2);
#pragma unroll
  for (int mf = 0; mf < 4; ++mf) {
    const int row0 = m0 + wm + mf * 16 + g;
#pragma unroll
    for (int nf = 0; nf < 4; ++nf) {
      const int col = n0 + wn + nf * 8 + tg * 2;
      float2 v0 = make_float2(acc[mf][nf][0] + bv[nf].x, acc[mf][nf][1] + bv[nf].y);
      float2 v1 = make_float2(acc[mf][nf][2] + bv[nf].x, acc[mf][nf][3] + bv[nf].y);
      *(float2*)(g_xw + (size_t)row0 * G4 + col) = v0;
      *(float2*)(g_xw + (size_t)(row0 + 8) * G4 + col) = v1;
    }
  }
}

// ---------------------------------------------------------------------------
// Persistent TC recurrence, batch-split into 4 groups of 16 rows x 32 CTAs.
// R12 structure + HALF-CTA dependency split: K-half kw polls only its 16
// producers (one parallel __all_sync round), stages its own 16x256 half,
// then bar.sync(1+kw,128). Scatter __syncthreads merges halves before gates.
// ---------------------------------------------------------------------------
#define GBATCH   16
#define RTHREADS 256
#define ASTR 516   // smem row stride (floats)
#define GSTR 68    // gate tile row stride (64 + 4 pad)

__device__ __forceinline__ float sigmoidf_(float x) {
  return __fdividef(1.0f, 1.0f + __expf(-x));
}
__device__ __forceinline__ float ftanh_(float x) {
  const float e = __expf(-2.0f * fabsf(x));
  const float r = __fdividef(1.0f - e, 1.0f + e);
  return copysignf(r, x);
}

__global__ __launch_bounds__(RTHREADS) void recur_tc_kernel(
    const float* __restrict__ U, float* __restrict__ out) {
  extern __shared__ float sm[];
  float* As = sm;                              // 16 x ASTR
  float* Us = sm + GBATCH * ASTR;              // 64 x ASTR
  float* Gs = sm + GBATCH * ASTR + 64 * ASTR;  // 2 x 16 x GSTR

  const int tid = threadIdx.x;
  const int lane = tid & 31, wid = tid >> 5;
  const int g = lane >> 2, tg = lane & 3;
  const int kw = wid >> 2;                 // K-half (0,1); tids [kw*128,+128)
  const int nq = wid & 3;                  // n-quarter (0..3)
  const int kb0 = kw * 256;
  const int group = blockIdx.x >> 5;       // 0..3 (batch group)
  const int cg = blockIdx.x & 31;          // CTA in group
  const int hb = cg * 16;                  // h-col base (16 h per CTA)
  const int b0 = group * GBATCH;           // global batch base
  unsigned* myflag = &g_flags[group][cg * 32];
  // half-split polling: this half depends only on producers kw*16..kw*16+15
  unsigned* pollp = &g_flags[group][(kw * 16 + (lane & 15)) * 32];
  const int ltid = tid & 127;              // tid within half

  // --- preload U slice (tf32): Us[i*4+gate][k] = U[k][gate*512+hb+i], i<16
  for (int idx = tid; idx < 512 * 4 * 4; idx += RTHREADS) {
    const int k = idx >> 4, gate = (idx >> 2) & 3, iq = idx & 3;
    float4 v = *(const float4*)(U + (size_t)k * G4 + gate * HID + hb + iq * 4);
    Us[((iq * 4 + 0) * 4 + gate) * ASTR + k] = f2tf32f(v.x);
    Us[((iq * 4 + 1) * 4 + gate) * ASTR + k] = f2tf32f(v.y);
    Us[((iq * 4 + 2) * 4 + gate) * ASTR + k] = f2tf32f(v.z);
    Us[((iq * 4 + 3) * 4 + gate) * ASTR + k] = f2tf32f(v.w);
  }

  // ldmatrix per-lane base offsets (bytes)
  const int quad = lane >> 3, r8 = lane & 7;
  const uint32_t As_u = smem_u32(As);
  const uint32_t Us_u = smem_u32(Us);
  const uint32_t a_base =
      As_u + ((((quad & 1) * 8 + r8) * ASTR + (quad >> 1) * 4 + kb0) * 4);
  const uint32_t b_base =
      Us_u + (((nq * 16 + (quad >> 1) * 8 + r8) * ASTR + (quad & 1) * 4 + kb0) * 4);

  // acc columns in xw space: n_local = nq*16 + nf*8 + 2tg (+1)
  int colA[2], colB[2];
#pragma unroll
  for (int nf = 0; nf < 2; ++nf) {
    const int nlA = nq * 16 + nf * 8 + 2 * tg, nlB = nlA + 1;
    colA[nf] = (nlA & 3) * HID + hb + (nlA >> 2);
    colB[nf] = (nlB & 3) * HID + hb + (nlB >> 2);
  }
  const int bl = tid >> 4;                 // gate-phase local batch (0..15)
  const int hi = tid & 15;                 // gate-phase h index (0..15)

  // --- prefetch xw for t=0 (K-half-0 warps hold the init)
  float pxw[8];
  if (kw == 0) {
    const float* xwp = g_xw + (size_t)(b0 + g) * G4;
#pragma unroll
    for (int nf = 0; nf < 2; ++nf) {
      pxw[nf * 4 + 0] = __ldg(xwp + colA[nf]);
      pxw[nf * 4 + 1] = __ldg(xwp + colB[nf]);
      pxw[nf * 4 + 2] = __ldg(xwp + 8 * G4 + colA[nf]);
      pxw[nf * 4 + 3] = __ldg(xwp + 8 * G4 + colB[nf]);
    }
  }

  for (int t = 0; t < T_STEPS; ++t) {
    // --- acc init
    float acc[2][4];
#pragma unroll
    for (int nf = 0; nf < 2; ++nf)
#pragma unroll
      for (int q = 0; q < 4; ++q)
        acc[nf][q] = (kw == 0) ? pxw[nf * 4 + q] : 0.0f;

    // --- half-split wait: this half's 16 producers finished step t-1
    {
      const unsigned tgt = (unsigned)t;
      unsigned v;
      do {
        asm volatile("ld.acquire.gpu.global.u32 %0, [%1];"
                     : "=r"(v) : "l"(pollp) : "memory");
      } while (!__all_sync(0xFFFFFFFFu, v >= tgt));
    }

    // --- stage this half's a_{t-1} block: 16 rows x cols [kb0, kb0+256)
    {
      const float* src = g_atf[t & 1] + (size_t)b0 * HID + kb0;
#pragma unroll
      for (int j = 0; j < 8; ++j) {
        const int idx = ltid + j * 128;    // 0..1023
        const int b = idx >> 6, c4 = idx & 63;
        float4 v = __ldcg((const float4*)(src + b * HID + c4 * 4));
        *(float4*)(As + b * ASTR + kb0 + c4 * 4) = v;
      }
    }
    // half-CTA convergence
    asm volatile("bar.sync %0, %1;" :: "r"(1 + kw), "r"(128) : "memory");

    // --- prefetch next step's xw while mma runs
    if (kw == 0 && t + 1 < T_STEPS) {
      const float* xwp = g_xw + (size_t)(t + 1) * BATCH * G4 + (size_t)(b0 + g) * G4;
#pragma unroll
      for (int nf = 0; nf < 2; ++nf) {
        pxw[nf * 4 + 0] = __ldg(xwp + colA[nf]);
        pxw[nf * 4 + 1] = __ldg(xwp + colB[nf]);
        pxw[nf * 4 + 2] = __ldg(xwp + 8 * G4 + colA[nf]);
        pxw[nf * 4 + 3] = __ldg(xwp + 8 * G4 + colB[nf]);
      }
    }

    // --- mma: m16 x n16 over this warp's K-half, ldmatrix fragment loads
#pragma unroll 8
    for (int k8 = 0; k8 < 32; ++k8) {
      uint32_t afr[4], bb[4];
      ldsm_x4(afr, a_base + k8 * 32);
      ldsm_x4(bb, b_base + k8 * 32);
      mma_tf32(acc[0], afr, bb);
      mma_tf32(acc[1], afr, bb + 2);
    }

    // --- scatter partial preactivations (per K-half region)
    float* Gsw = Gs + kw * GBATCH * GSTR;
#pragma unroll
    for (int nf = 0; nf < 2; ++nf) {
      const int nb = nq * 16 + nf * 8 + 2 * tg;
      *(float2*)(Gsw + g * GSTR + nb) = make_float2(acc[nf][0], acc[nf][1]);
      *(float2*)(Gsw + (g + 8) * GSTR + nb) = make_float2(acc[nf][2], acc[nf][3]);
    }
    __syncthreads();  // merges both halves: all 32 producer waits + staging

    // --- gate math: 1 output/thread (b=bl, h=hb+hi); sum the two K-halves
    {
      float4 gA = *(const float4*)(Gs + bl * GSTR + hi * 4);
      float4 gB = *(const float4*)(Gs + GBATCH * GSTR + bl * GSTR + hi * 4);
      const float gu = sigmoidf_(gA.x + gB.x);
      const float gf = sigmoidf_(gA.y + gB.y);
      const float go = sigmoidf_(gA.z + gB.z);
      const float cd = ftanh_(gA.w + gB.w);
      const float ap = As[bl * ASTR + hb + hi];  // tf32-rounded a_{t-1}
      const float ct = gu * cd + gf * ap;
      const float at = go * ftanh_(ct);
      g_atf[(t + 1) & 1][(b0 + bl) * HID + hb + hi] = f2tf32f(at);
      out[(size_t)t * BATCH * HID + (size_t)(b0 + bl) * HID + hb + hi] = at;
    }

    // --- release: this CTA fully done with step t
    if (t + 1 < T_STEPS) {
      __syncthreads();  // orders all threads' writes before tid0's release
      if (tid == 0) {
        unsigned v = (unsigned)(t + 1);
        asm volatile("st.release.gpu.global.u32 [%0], %1;"
                     :: "l"(myflag), "r"(v) : "memory");
      }
    }
  }
}

// ---------------------------------------------------------------------------
extern "C" void kernel_launch(void* const* d_in, const int* in_sizes, int n_in,
                              void* d_out, int out_size) {
  (void)in_sizes; (void)n_in; (void)out_size;
  const float* x    = (const float*)d_in[0];  // [T, B, I]
  const float* a0   = (const float*)d_in[1];  // [B, H]
  const float* W    = (const float*)d_in[2];  // [I, 4H]
  const float* U    = (const float*)d_in[3];  // [H, 4H]
  const float* bias = (const float*)d_in[4];  // [4H]
  float* out = (float*)d_out;                 // [T, B, H]

  const int smemG = 4 * BM * SSTR * sizeof(float);  // 73728 B
  cudaFuncSetAttribute(xw_tc_kernel, cudaFuncAttributeMaxDynamicSharedMemorySize,
                       smemG);
  const int smemR =
      (GBATCH * ASTR + 64 * ASTR + 2 * GBATCH * GSTR) * sizeof(float);  // 173824
  cudaFuncSetAttribute(recur_tc_kernel, cudaFuncAttributeMaxDynamicSharedMemorySize,
                       smemR);

  transpose_kernel<<<dim3(G4 / 32, INDIM / 32), dim3(32, 8)>>>(W, a0);
  xw_tc_kernel<<<dim3(G4 / BN, (T_STEPS * BATCH) / BM), 256, smemG>>>(x, bias);
  recur_tc_kernel<<<NGROUPS * GCTAS, RTHREADS, smemR>>>(U, out);
}

// round 17
// speedup vs baseline: 2.2709x; 1.3484x over previous
#include <cuda_runtime.h>
#include <cstdint>
#include <cstddef>

#define T_STEPS 512
#define BATCH   64
#define INDIM   512
#define HID     512
#define G4      2048   // 4*HID

// scratch: precomputed x@W+b, transposed tf32 W, ping-pong tf32 hidden state
__device__ float g_xw[(size_t)T_STEPS * BATCH * G4];
__device__ float g_Wt[(size_t)G4 * INDIM];
__device__ float g_atf[2][BATCH * HID];
#define NGROUPS 4
#define GCTAS   32
// per-CTA barrier flags, each on its own 128B line: g_flags[group][cta*32]
__device__ unsigned g_flags[NGROUPS][GCTAS * 32];

__device__ __forceinline__ uint32_t f2tf32(float f) {
  uint32_t r;
  asm("cvt.rna.tf32.f32 %0, %1;" : "=r"(r) : "f"(f));
  return r;
}
__device__ __forceinline__ float f2tf32f(float f) {
  return __uint_as_float(f2tf32(f));
}
__device__ __forceinline__ uint32_t smem_u32(const void* p) {
  uint32_t a;
  asm("{ .reg .u64 t; cvta.to.shared.u64 t, %1; cvt.u32.u64 %0, t; }"
      : "=r"(a) : "l"(p));
  return a;
}
__device__ __forceinline__ void ldsm_x4(uint32_t* d, uint32_t addr) {
  asm volatile("ldmatrix.sync.aligned.m8n8.x4.shared.b16 {%0,%1,%2,%3}, [%4];"
               : "=r"(d[0]), "=r"(d[1]), "=r"(d[2]), "=r"(d[3]) : "r"(addr));
}

__device__ __forceinline__ void mma_tf32(float* d, const uint32_t* a,
                                         const uint32_t* b) {
  asm volatile(
      "mma.sync.aligned.m16n8k8.row.col.f32.tf32.tf32.f32 "
      "{%0,%1,%2,%3}, {%4,%5,%6,%7}, {%8,%9}, {%0,%1,%2,%3};"
      : "+f"(d[0]), "+f"(d[1]), "+f"(d[2]), "+f"(d[3])
      : "r"(a[0]), "r"(a[1]), "r"(a[2]), "r"(a[3]), "r"(b[0]), "r"(b[1]));
}

// ---------------------------------------------------------------------------
// W transpose + tf32 rounding; rounds a0 into g_atf[0]; zeroes barrier flags.
// ---------------------------------------------------------------------------
__global__ __launch_bounds__(256) void transpose_kernel(const float* __restrict__ W,
                                                        const float* __restrict__ a0) {
  __shared__ float tile[32][33];
  const int n0 = blockIdx.x * 32, k0 = blockIdx.y * 32;
  const int tx = threadIdx.x, ty = threadIdx.y;  // 32 x 8
#pragma unroll
  for (int i = 0; i < 32; i += 8)
    tile[ty + i][tx] = W[(size_t)(k0 + ty + i) * G4 + n0 + tx];
  __syncthreads();
#pragma unroll
  for (int i = 0; i < 32; i += 8)
    g_Wt[(size_t)(n0 + ty + i) * INDIM + k0 + tx] = f2tf32f(tile[tx][ty + i]);
  if (blockIdx.y == 0) {  // 64 blocks x 256 thr: round a0 (32768 elems)
    const int fl = blockIdx.x * 256 + ty * 32 + tx;
    g_atf[0][fl] = f2tf32f(a0[fl]);
    g_atf[0][fl + 16384] = f2tf32f(a0[fl + 16384]);
  }
  if (blockIdx.x == 0 && blockIdx.y == 0) {  // zero all flags (4096 u32)
    const int lt = ty * 32 + tx;
#pragma unroll
    for (int j = 0; j < NGROUPS * GCTAS * 32 / 256; ++j)
      ((unsigned*)g_flags)[lt + j * 256] = 0u;
  }
}

// ---------------------------------------------------------------------------
// TF32 tensor-core GEMM (unchanged, known-good): g_xw = x@W + bias
// ---------------------------------------------------------------------------
#define BM 128
#define BN 128
#define BK 32
#define SSTR 36

__global__ __launch_bounds__(256) void xw_tc_kernel(const float* __restrict__ A,
                                                    const float* __restrict__ bias) {
  extern __shared__ float smem[];
  float* As[2] = {smem, smem + BM * SSTR};
  float* Bs[2] = {smem + 2 * BM * SSTR, smem + 3 * BM * SSTR};

  const int tid = threadIdx.x;
  const int lane = tid & 31, wid = tid >> 5;
  const int wm = (wid >> 2) * 64;
  const int wn = (wid & 3) * 32;
  const int g = lane >> 2, tg = lane & 3;
  const int n0 = blockIdx.x * BN;
  const int m0 = blockIdx.y * BM;

  const int lr = tid >> 3;
  const int lc = (tid & 7) * 4;

  float acc[4][4][4];
#pragma unroll
  for (int i = 0; i < 4; ++i)
#pragma unroll
    for (int j = 0; j < 4; ++j)
#pragma unroll
      for (int q = 0; q < 4; ++q) acc[i][j][q] = 0.0f;

  float4 pa[4], pb[4];
#pragma unroll
  for (int j = 0; j < 4; ++j) {
    const int r = lr + j * 32;
    pa[j] = *(const float4*)(A + (size_t)(m0 + r) * INDIM + lc);
    pb[j] = *(const float4*)(g_Wt + (size_t)(n0 + r) * INDIM + lc);
  }

  const int NKT = INDIM / BK;  // 16
  for (int kt = 0; kt < NKT; ++kt) {
    const int s = kt & 1;
#pragma unroll
    for (int j = 0; j < 4; ++j) {
      const int r = lr + j * 32;
      float* ap = As[s] + r * SSTR + lc;
      ap[0] = f2tf32f(pa[j].x);
      ap[1] = f2tf32f(pa[j].y);
      ap[2] = f2tf32f(pa[j].z);
      ap[3] = f2tf32f(pa[j].w);
      *(float4*)(Bs[s] + r * SSTR + lc) = pb[j];
    }
    __syncthreads();

    if (kt + 1 < NKT) {
      const int ko = (kt + 1) * BK;
#pragma unroll
      for (int j = 0; j < 4; ++j) {
        const int r = lr + j * 32;
        pa[j] = *(const float4*)(A + (size_t)(m0 + r) * INDIM + ko + lc);
        pb[j] = *(const float4*)(g_Wt + (size_t)(n0 + r) * INDIM + ko + lc);
      }
    }

#pragma unroll
    for (int k8 = 0; k8 < 4; ++k8) {
      const int kb = k8 * 8;
      uint32_t afr[4][4], bfr[4][2];
#pragma unroll
      for (int mf = 0; mf < 4; ++mf) {
        const float* ap = As[s] + (wm + mf * 16) * SSTR + kb;
        afr[mf][0] = __float_as_uint(ap[g * SSTR + tg]);
        afr[mf][1] = __float_as_uint(ap[(g + 8) * SSTR + tg]);
        afr[mf][2] = __float_as_uint(ap[g * SSTR + tg + 4]);
        afr[mf][3] = __float_as_uint(ap[(g + 8) * SSTR + tg + 4]);
      }
#pragma unroll
      for (int nf = 0; nf < 4; ++nf) {
        const float* bp = Bs[s] + (wn + nf * 8) * SSTR + kb;
        bfr[nf][0] = __float_as_uint(bp[g * SSTR + tg]);
        bfr[nf][1] = __float_as_uint(bp[g * SSTR + tg + 4]);
      }
#pragma unroll
      for (int mf = 0; mf < 4; ++mf)
#pragma unroll
        for (int nf = 0; nf < 4; ++nf)
          mma_tf32(acc[mf][nf], afr[mf], bfr[nf]);
    }
    __syncthreads();
  }

  float2 bv[4];
#pragma unroll
  for (int nf = 0; nf < 4; ++nf)
    bv[nf] = *(const float2*)(bias + n0 + wn + nf * 8 + tg * 2);
#pragma unroll
  for (int mf = 0; mf < 4; ++mf) {
    const int row0 = m0 + wm + mf * 16 + g;
#pragma unroll
    for (int nf = 0; nf < 4; ++nf) {
      const int col = n0 + wn + nf * 8 + tg * 2;
      float2 v0 = make_float2(acc[mf][nf][0] + bv[nf].x, acc[mf][nf][1] + bv[nf].y);
      float2 v1 = make_float2(acc[mf][nf][2] + bv[nf].x, acc[mf][nf][3] + bv[nf].y);
      *(float2*)(g_xw + (size_t)row0 * G4 + col) = v0;
      *(float2*)(g_xw + (size_t)(row0 + 8) * G4 + col) = v1;
    }
  }
}

// ---------------------------------------------------------------------------
// Persistent TC recurrence, batch-split into 4 groups of 16 rows x 32 CTAs.
// This round: warp = m16 x n32 x k128 (4 K-quarters x 2 n-halves); U (B)
// fragments preloaded into 128 persistent registers per lane -> ZERO B smem
// traffic in the t-loop. Quarter kq polls only its 8 producers.
// ---------------------------------------------------------------------------
#define GBATCH   16
#define RTHREADS 256
#define ASTR 516   // smem row stride (floats)
#define GSTR 68    // gate tile row stride (64 + 4 pad)

__device__ __forceinline__ float sigmoidf_(float x) {
  return __fdividef(1.0f, 1.0f + __expf(-x));
}
__device__ __forceinline__ float ftanh_(float x) {
  const float e = __expf(-2.0f * fabsf(x));
  const float r = __fdividef(1.0f - e, 1.0f + e);
  return copysignf(r, x);
}

__global__ __launch_bounds__(RTHREADS, 1) void recur_tc_kernel(
    const float* __restrict__ U, float* __restrict__ out) {
  extern __shared__ float sm[];
  float* As = sm;                              // 16 x ASTR
  float* Us = sm + GBATCH * ASTR;              // 64 x ASTR
  float* Gs = sm + GBATCH * ASTR + 64 * ASTR;  // 4 x 16 x GSTR

  const int tid = threadIdx.x;
  const int lane = tid & 31, wid = tid >> 5;
  const int g = lane >> 2, tg = lane & 3;
  const int kq = wid >> 1;                 // K-quarter (0..3); tids [kq*64,+64)
  const int nh = wid & 1;                  // n-half (0..1)
  const int kb0 = kq * 128;
  const int group = blockIdx.x >> 5;       // 0..3 (batch group)
  const int cg = blockIdx.x & 31;          // CTA in group
  const int hb = cg * 16;                  // h-col base (16 h per CTA)
  const int b0 = group * GBATCH;           // global batch base
  unsigned* myflag = &g_flags[group][cg * 32];
  // quarter-split polling: quarter kq depends only on producers kq*8..kq*8+7
  unsigned* pollp = &g_flags[group][(kq * 8 + (lane & 7)) * 32];
  const int ltid = tid & 63;               // tid within quarter

  // --- preload U slice (tf32): Us[i*4+gate][k] = U[k][gate*512+hb+i], i<16
  for (int idx = tid; idx < 512 * 4 * 4; idx += RTHREADS) {
    const int k = idx >> 4, gate = (idx >> 2) & 3, iq = idx & 3;
    float4 v = *(const float4*)(U + (size_t)k * G4 + gate * HID + hb + iq * 4);
    Us[((iq * 4 + 0) * 4 + gate) * ASTR + k] = f2tf32f(v.x);
    Us[((iq * 4 + 1) * 4 + gate) * ASTR + k] = f2tf32f(v.y);
    Us[((iq * 4 + 2) * 4 + gate) * ASTR + k] = f2tf32f(v.z);
    Us[((iq * 4 + 3) * 4 + gate) * ASTR + k] = f2tf32f(v.w);
  }
  __syncthreads();  // Us complete before ANY fragment preload (fixes R16 race)

  // ldmatrix per-lane base offsets (bytes)
  const int quad = lane >> 3, r8 = lane & 7;
  const uint32_t As_u = smem_u32(As);
  const uint32_t Us_u = smem_u32(Us);
  const uint32_t a_base =
      As_u + ((((quad & 1) * 8 + r8) * ASTR + (quad >> 1) * 4 + kb0) * 4);
  const uint32_t b_base0 =
      Us_u + (((nh * 32 + 0 + (quad >> 1) * 8 + r8) * ASTR + (quad & 1) * 4 + kb0) * 4);
  const uint32_t b_base1 =
      Us_u + (((nh * 32 + 16 + (quad >> 1) * 8 + r8) * ASTR + (quad & 1) * 4 + kb0) * 4);

  // --- persistent B (U) fragments: n32 x k128 per warp = 128 regs/lane
  uint32_t bU[16][8];
#pragma unroll
  for (int f = 0; f < 16; ++f) {
    ldsm_x4(&bU[f][0], b_base0 + f * 32);
    ldsm_x4(&bU[f][4], b_base1 + f * 32);
  }

  // acc columns in xw space: n_local = nh*32 + nf*8 + 2tg (+1), nf = 0..3
  int colA[4], colB[4];
#pragma unroll
  for (int nf = 0; nf < 4; ++nf) {
    const int nlA = nh * 32 + nf * 8 + 2 * tg, nlB = nlA + 1;
    colA[nf] = (nlA & 3) * HID + hb + (nlA >> 2);
    colB[nf] = (nlB & 3) * HID + hb + (nlB >> 2);
  }
  const int bl = tid >> 4;                 // gate-phase local batch (0..15)
  const int hi = tid & 15;                 // gate-phase h index (0..15)

  // --- prefetch xw for t=0 (K-quarter-0 warps hold the init)
  float pxw[16];
  if (kq == 0) {
    const float* xwp = g_xw + (size_t)(b0 + g) * G4;
#pragma unroll
    for (int nf = 0; nf < 4; ++nf) {
      pxw[nf * 4 + 0] = __ldg(xwp + colA[nf]);
      pxw[nf * 4 + 1] = __ldg(xwp + colB[nf]);
      pxw[nf * 4 + 2] = __ldg(xwp + 8 * G4 + colA[nf]);
      pxw[nf * 4 + 3] = __ldg(xwp + 8 * G4 + colB[nf]);
    }
  }

  for (int t = 0; t < T_STEPS; ++t) {
    // --- acc init
    float acc[4][4];
#pragma unroll
    for (int nf = 0; nf < 4; ++nf)
#pragma unroll
      for (int q = 0; q < 4; ++q)
        acc[nf][q] = (kq == 0) ? pxw[nf * 4 + q] : 0.0f;

    // --- quarter-split wait: this quarter's 8 producers finished step t-1
    {
      const unsigned tgt = (unsigned)t;
      unsigned v;
      do {
        asm volatile("ld.acquire.gpu.global.u32 %0, [%1];"
                     : "=r"(v) : "l"(pollp) : "memory");
      } while (!__all_sync(0xFFFFFFFFu, v >= tgt));
    }

    // --- stage this quarter's a_{t-1} block: 16 rows x cols [kb0, kb0+128)
    {
      const float* src = g_atf[t & 1] + (size_t)b0 * HID + kb0;
#pragma unroll
      for (int j = 0; j < 8; ++j) {
        const int idx = ltid + j * 64;     // 0..511
        const int b = idx >> 5, c4 = idx & 31;
        float4 v = __ldcg((const float4*)(src + b * HID + c4 * 4));
        *(float4*)(As + b * ASTR + kb0 + c4 * 4) = v;
      }
    }
    // quarter convergence (2 warps, 64 threads)
    asm volatile("bar.sync %0, %1;" :: "r"(1 + kq), "r"(64) : "memory");

    // --- prefetch next step's xw while mma runs
    if (kq == 0 && t + 1 < T_STEPS) {
      const float* xwp = g_xw + (size_t)(t + 1) * BATCH * G4 + (size_t)(b0 + g) * G4;
#pragma unroll
      for (int nf = 0; nf < 4; ++nf) {
        pxw[nf * 4 + 0] = __ldg(xwp + colA[nf]);
        pxw[nf * 4 + 1] = __ldg(xwp + colB[nf]);
        pxw[nf * 4 + 2] = __ldg(xwp + 8 * G4 + colA[nf]);
        pxw[nf * 4 + 3] = __ldg(xwp + 8 * G4 + colB[nf]);
      }
    }

    // --- mma: m16 x n32 x k128; A from smem (16 ldsm), B from registers
#pragma unroll
    for (int f = 0; f < 16; ++f) {
      uint32_t afr[4];
      ldsm_x4(afr, a_base + f * 32);
      mma_tf32(acc[0], afr, &bU[f][0]);
      mma_tf32(acc[1], afr, &bU[f][2]);
      mma_tf32(acc[2], afr, &bU[f][4]);
      mma_tf32(acc[3], afr, &bU[f][6]);
    }

    // --- scatter partial preactivations (per K-quarter region)
    float* Gsw = Gs + kq * GBATCH * GSTR;
#pragma unroll
    for (int nf = 0; nf < 4; ++nf) {
      const int nb = nh * 32 + nf * 8 + 2 * tg;
      *(float2*)(Gsw + g * GSTR + nb) = make_float2(acc[nf][0], acc[nf][1]);
      *(float2*)(Gsw + (g + 8) * GSTR + nb) = make_float2(acc[nf][2], acc[nf][3]);
    }
    __syncthreads();  // merges all 4 quarters: all 32 producer waits + staging

    // --- gate math: 1 output/thread (b=bl, h=hb+hi); sum the 4 K-quarters
    {
      float4 g0 = *(const float4*)(Gs + 0 * GBATCH * GSTR + bl * GSTR + hi * 4);
      float4 g1 = *(const float4*)(Gs + 1 * GBATCH * GSTR + bl * GSTR + hi * 4);
      float4 g2 = *(const float4*)(Gs + 2 * GBATCH * GSTR + bl * GSTR + hi * 4);
      float4 g3 = *(const float4*)(Gs + 3 * GBATCH * GSTR + bl * GSTR + hi * 4);
      const float gu = sigmoidf_((g0.x + g1.x) + (g2.x + g3.x));
      const float gf = sigmoidf_((g0.y + g1.y) + (g2.y + g3.y));
      const float go = sigmoidf_((g0.z + g1.z) + (g2.z + g3.z));
      const float cd = ftanh_((g0.w + g1.w) + (g2.w + g3.w));
      const float ap = As[bl * ASTR + hb + hi];  // tf32-rounded a_{t-1}
      const float ct = gu * cd + gf * ap;
      const float at = go * ftanh_(ct);
      g_atf[(t + 1) & 1][(b0 + bl) * HID + hb + hi] = f2tf32f(at);
      out[(size_t)t * BATCH * HID + (size_t)(b0 + bl) * HID + hb + hi] = at;
    }

    // --- release: this CTA fully done with step t
    if (t + 1 < T_STEPS) {
      __syncthreads();  // orders all threads' writes before tid0's release
      if (tid == 0) {
        unsigned v = (unsigned)(t + 1);
        asm volatile("st.release.gpu.global.u32 [%0], %1;"
                     :: "l"(myflag), "r"(v) : "memory");
      }
    }
  }
}

// ---------------------------------------------------------------------------
extern "C" void kernel_launch(void* const* d_in, const int* in_sizes, int n_in,
                              void* d_out, int out_size) {
  (void)in_sizes; (void)n_in; (void)out_size;
  const float* x    = (const float*)d_in[0];  // [T, B, I]
  const float* a0   = (const float*)d_in[1];  // [B, H]
  const float* W    = (const float*)d_in[2];  // [I, 4H]
  const float* U    = (const float*)d_in[3];  // [H, 4H]
  const float* bias = (const float*)d_in[4];  // [4H]
  float* out = (float*)d_out;                 // [T, B, H]

  const int smemG = 4 * BM * SSTR * sizeof(float);  // 73728 B
  cudaFuncSetAttribute(xw_tc_kernel, cudaFuncAttributeMaxDynamicSharedMemorySize,
                       smemG);
  const int smemR =
      (GBATCH * ASTR + 64 * ASTR + 4 * GBATCH * GSTR) * sizeof(float);  // 182528
  cudaFuncSetAttribute(recur_tc_kernel, cudaFuncAttributeMaxDynamicSharedMemorySize,
                       smemR);

  transpose_kernel<<<dim3(G4 / 32, INDIM / 32), dim3(32, 8)>>>(W, a0);
  xw_tc_kernel<<<dim3(G4 / BN, (T_STEPS * BATCH) / BM), 256, smemG>>>(x, bias);
  recur_tc_kernel<<<NGROUPS * GCTAS, RTHREADS, smemR>>>(U, out);
}